// round 2
// baseline (speedup 1.0000x reference)
#include <cuda_runtime.h>
#include <cuda_bf16.h>
#include <math.h>

// TopK router: logits = X[16384,4096] @ W[64,4096]^T, top-2, softmax over top-2.
// fp32 accumulation via packed fma.rn.f32x2 (FFMA2): accumulator holds two
// partial sums over (even-k, odd-k); final logit = lo + hi.
//
// Output layout assumption: d_out = [topk_scores (tokens*2 f32)] ++
//                                   [topk_indices (tokens*2, as f32)]

#define DIM       4096
#define NEXP      64
#define KT        32            // K-chunk
#define TOK_CTA   64            // tokens per CTA
#define THREADS   256
#define XROW      36            // padded row stride (floats) for X/W tiles
#define LROW      65            // padded row stride for logits tile

__device__ __forceinline__ void fma2(unsigned long long &acc,
                                     unsigned long long x,
                                     unsigned long long w) {
    asm("fma.rn.f32x2 %0, %1, %2, %0;" : "+l"(acc) : "l"(x), "l"(w));
}

__device__ __forceinline__ float acc_sum(unsigned long long a) {
    float lo = __uint_as_float((unsigned)(a & 0xffffffffULL));
    float hi = __uint_as_float((unsigned)(a >> 32));
    return lo + hi;
}

__global__ __launch_bounds__(THREADS)
void topk_router_kernel(const float* __restrict__ X,
                        const float* __restrict__ W,
                        float* __restrict__ out,
                        int n_tokens, int out_size) {
    __shared__ __align__(16) unsigned char pool[2 * TOK_CTA * XROW * 4 * 2]; // 36864 B

    float* Xs = (float*)pool;                                  // [2][64][36]
    float* Ws = (float*)(pool + 2 * TOK_CTA * XROW * 4);       // [2][64][36]

    const int tid = threadIdx.x;
    const int m0  = blockIdx.x * TOK_CTA;

    // loader mapping: row = tid/8 (+32 per iter), col4 = tid%8  (coalesced 128B)
    const int lrow = tid >> 3;
    const int lc4  = tid & 7;

    // compute mapping: token t0 and t0+32, experts h*8 .. h*8+7
    const int t0 = tid & 31;
    const int h  = tid >> 5;

    unsigned long long acc[2][8];
#pragma unroll
    for (int t = 0; t < 2; t++)
#pragma unroll
        for (int j = 0; j < 8; j++) acc[t][j] = 0ULL;

    // ---- prologue: load chunk 0 into buffer 0 ----
    {
        const float* xg0 = X + (size_t)(m0 + lrow)      * DIM + lc4 * 4;
        const float* xg1 = X + (size_t)(m0 + lrow + 32) * DIM + lc4 * 4;
        const float* wg0 = W + (size_t)(lrow)      * DIM + lc4 * 4;
        const float* wg1 = W + (size_t)(lrow + 32) * DIM + lc4 * 4;
        float4 a = *(const float4*)xg0;
        float4 b = *(const float4*)xg1;
        float4 c = *(const float4*)wg0;
        float4 d = *(const float4*)wg1;
        *(float4*)&Xs[(lrow)      * XROW + lc4 * 4] = a;
        *(float4*)&Xs[(lrow + 32) * XROW + lc4 * 4] = b;
        *(float4*)&Ws[(lrow)      * XROW + lc4 * 4] = c;
        *(float4*)&Ws[(lrow + 32) * XROW + lc4 * 4] = d;
    }
    __syncthreads();

    const int nchunks = DIM / KT;   // 128
    int p = 0;

    for (int ch = 0; ch < nchunks; ch++) {
        float4 ra, rb, rc, rd;
        const bool more = (ch + 1 < nchunks);
        if (more) {
            const int kt = (ch + 1) * KT;
            const float* xg0 = X + (size_t)(m0 + lrow)      * DIM + kt + lc4 * 4;
            const float* xg1 = X + (size_t)(m0 + lrow + 32) * DIM + kt + lc4 * 4;
            const float* wg0 = W + (size_t)(lrow)      * DIM + kt + lc4 * 4;
            const float* wg1 = W + (size_t)(lrow + 32) * DIM + kt + lc4 * 4;
            ra = *(const float4*)xg0;
            rb = *(const float4*)xg1;
            rc = *(const float4*)wg0;
            rd = *(const float4*)wg1;
        }

        const float* xb = Xs + p * TOK_CTA * XROW;
        const float* wb = Ws + p * TOK_CTA * XROW;

#pragma unroll
        for (int k4 = 0; k4 < KT / 4; k4++) {
            ulonglong2 xA = *(const ulonglong2*)&xb[(t0)      * XROW + k4 * 4];
            ulonglong2 xB = *(const ulonglong2*)&xb[(t0 + 32) * XROW + k4 * 4];
#pragma unroll
            for (int j = 0; j < 8; j++) {
                ulonglong2 w = *(const ulonglong2*)&wb[(h * 8 + j) * XROW + k4 * 4];
                fma2(acc[0][j], xA.x, w.x);
                fma2(acc[0][j], xA.y, w.y);
                fma2(acc[1][j], xB.x, w.x);
                fma2(acc[1][j], xB.y, w.y);
            }
        }
        __syncthreads();
        if (more) {
            const int q = p ^ 1;
            float* xq = Xs + q * TOK_CTA * XROW;
            float* wq = Ws + q * TOK_CTA * XROW;
            *(float4*)&xq[(lrow)      * XROW + lc4 * 4] = ra;
            *(float4*)&xq[(lrow + 32) * XROW + lc4 * 4] = rb;
            *(float4*)&wq[(lrow)      * XROW + lc4 * 4] = rc;
            *(float4*)&wq[(lrow + 32) * XROW + lc4 * 4] = rd;
            __syncthreads();
            p = q;
        }
    }

    // ---- epilogue: gather logits to smem, top-2 + softmax ----
    __syncthreads();   // all compute reads done; safe to alias pool
    float* Ls = (float*)pool;   // [64][65]
#pragma unroll
    for (int j = 0; j < 8; j++) {
        Ls[(t0)      * LROW + h * 8 + j] = acc_sum(acc[0][j]);
        Ls[(t0 + 32) * LROW + h * 8 + j] = acc_sum(acc[1][j]);
    }
    __syncthreads();

    if (tid < TOK_CTA) {
        const float* row = Ls + tid * LROW;
        float v1 = -INFINITY, v2 = -INFINITY;
        int i1 = 0, i2 = 0;
#pragma unroll 8
        for (int e = 0; e < NEXP; e++) {
            float v = row[e];
            if (v > v1) { v2 = v1; i2 = i1; v1 = v; i1 = e; }
            else if (v > v2) { v2 = v; i2 = e; }
        }
        float e2 = expf(v2 - v1);
        float inv = 1.0f / (1.0f + e2);
        float s1 = inv;
        float s2 = e2 * inv;

        const int g = m0 + tid;
        out[g * 2 + 0] = s1;
        out[g * 2 + 1] = s2;
        const int sc = n_tokens * 2;       // 32768
        if (out_size >= 2 * sc) {
            out[sc + g * 2 + 0] = (float)i1;
            out[sc + g * 2 + 1] = (float)i2;
        }
    }
}

extern "C" void kernel_launch(void* const* d_in, const int* in_sizes, int n_in,
                              void* d_out, int out_size) {
    const float* X = (const float*)d_in[0];
    const float* W = (const float*)d_in[1];
    float* out = (float*)d_out;

    const int n_tokens = in_sizes[0] / DIM;       // 16384
    const int grid = n_tokens / TOK_CTA;          // 256

    topk_router_kernel<<<grid, THREADS>>>(X, W, out, n_tokens, out_size);
}

// round 4
// speedup vs baseline: 1.3546x; 1.3546x over previous
#include <cuda_runtime.h>
#include <cuda_bf16.h>
#include <cstdint>
#include <math.h>

// TopK router: logits = X[16384,4096] @ W[64,4096]^T, top-2 + softmax.
// fp32-accurate GEMM via 6-term 3-level bf16 split on portable HMMA
// (mma.sync.m16n8k16) -- tcgen05 is unavailable (ptxas target sm_103, no 'a').

#define DIM     4096
#define NEXP    64
#define MTILE   128
#define KC      64
#define NCH     (DIM / KC)      // 64
#define THREADS 256

// smem stage layout (bf16 tiles, 128B row stride, SW128 swizzle)
#define X0_OFF  0
#define X1_OFF  16384
#define X2_OFF  32768
#define W0_OFF  49152
#define W1_OFF  57344
#define W2_OFF  65536
#define STAGE_SZ 73728
#define SMEM_TOTAL (2 * STAGE_SZ)   // 147456

__device__ __nv_bfloat16 g_w0[NEXP * DIM];
__device__ __nv_bfloat16 g_w1[NEXP * DIM];
__device__ __nv_bfloat16 g_w2[NEXP * DIM];

// ---------- helpers ----------
__device__ __forceinline__ uint32_t smem_u32(const void* p) {
    uint32_t a;
    asm("{ .reg .u64 t; cvta.to.shared.u64 t, %1; cvt.u32.u64 %0, t; }" : "=r"(a) : "l"(p));
    return a;
}
__device__ __forceinline__ uint32_t swz(uint32_t o) { return o ^ ((o >> 3) & 0x70); }

__device__ __forceinline__ uint32_t pack_bf16(float hi, float lo) {
    uint32_t r;
    asm("cvt.rn.bf16x2.f32 %0, %1, %2;" : "=r"(r) : "f"(hi), "f"(lo));
    return r;
}
__device__ __forceinline__ float lo_f(uint32_t h) { return __uint_as_float(h << 16); }
__device__ __forceinline__ float hi_f(uint32_t h) { return __uint_as_float(h & 0xffff0000u); }

__device__ __forceinline__ void sts64(uint32_t a, uint32_t x, uint32_t y) {
    asm volatile("st.shared.v2.b32 [%0], {%1, %2};" :: "r"(a), "r"(x), "r"(y) : "memory");
}
__device__ __forceinline__ void sts128(uint32_t a, uint4 v) {
    asm volatile("st.shared.v4.b32 [%0], {%1, %2, %3, %4};"
                 :: "r"(a), "r"(v.x), "r"(v.y), "r"(v.z), "r"(v.w) : "memory");
}
__device__ __forceinline__ void ldsm4(uint32_t r[4], uint32_t addr) {
    asm volatile("ldmatrix.sync.aligned.m8n8.x4.shared.b16 {%0,%1,%2,%3}, [%4];"
                 : "=r"(r[0]), "=r"(r[1]), "=r"(r[2]), "=r"(r[3]) : "r"(addr));
}
__device__ __forceinline__ void mma16816(float d[4], const uint32_t a[4],
                                         uint32_t b0, uint32_t b1) {
    asm volatile("mma.sync.aligned.m16n8k16.row.col.f32.bf16.bf16.f32 "
                 "{%0,%1,%2,%3}, {%4,%5,%6,%7}, {%8,%9}, {%0,%1,%2,%3};"
                 : "+f"(d[0]), "+f"(d[1]), "+f"(d[2]), "+f"(d[3])
                 : "r"(a[0]), "r"(a[1]), "r"(a[2]), "r"(a[3]), "r"(b0), "r"(b1));
}

// ---------- W 3-level split prep ----------
__global__ void prep_w(const float* __restrict__ W) {
    int i = (blockIdx.x * blockDim.x + threadIdx.x) * 4;
    float4 v = *(const float4*)(W + i);
    float vv[4] = {v.x, v.y, v.z, v.w};
#pragma unroll
    for (int j = 0; j < 4; j++) {
        float x = vv[j];
        __nv_bfloat16 h0 = __float2bfloat16(x);
        float r0 = x - __bfloat162float(h0);
        __nv_bfloat16 h1 = __float2bfloat16(r0);
        float r1 = r0 - __bfloat162float(h1);
        __nv_bfloat16 h2 = __float2bfloat16(r1);
        g_w0[i + j] = h0;
        g_w1[i + j] = h1;
        g_w2[i + j] = h2;
    }
}

// ---------- staging ----------
struct StageRegs {
    float4 x[8];
    uint4  w0[2], w1[2], w2[2];
};

__device__ __forceinline__ void load_stage(const float* __restrict__ X, int m0, int s,
                                           int u, int tb, int tid, StageRegs& r) {
    const int k0 = s * KC;
#pragma unroll
    for (int i = 0; i < 8; i++)
        r.x[i] = *(const float4*)(X + (size_t)(m0 + tb + i * 16) * DIM + k0 + u * 4);
#pragma unroll
    for (int i = 0; i < 2; i++) {
        int uw = tid * 2 + i;
        int row = uw >> 3, c = uw & 7;
        size_t gi = (size_t)row * DIM + k0 + c * 8;
        r.w0[i] = *(const uint4*)(g_w0 + gi);
        r.w1[i] = *(const uint4*)(g_w1 + gi);
        r.w2[i] = *(const uint4*)(g_w2 + gi);
    }
}

__device__ __forceinline__ void store_stage(uint32_t tbase, int u, int tb, int tid,
                                            const StageRegs& r) {
#pragma unroll
    for (int i = 0; i < 8; i++) {
        float4 v = r.x[i];
        // level 0
        uint32_t a0 = pack_bf16(v.y, v.x);
        uint32_t a1 = pack_bf16(v.w, v.z);
        float r0x = v.x - lo_f(a0), r0y = v.y - hi_f(a0);
        float r0z = v.z - lo_f(a1), r0w = v.w - hi_f(a1);
        // level 1
        uint32_t b0 = pack_bf16(r0y, r0x);
        uint32_t b1 = pack_bf16(r0w, r0z);
        float r1x = r0x - lo_f(b0), r1y = r0y - hi_f(b0);
        float r1z = r0z - lo_f(b1), r1w = r0w - hi_f(b1);
        // level 2
        uint32_t c0 = pack_bf16(r1y, r1x);
        uint32_t c1 = pack_bf16(r1w, r1z);

        uint32_t o = swz((uint32_t)((tb + i * 16) * 128 + u * 8));
        sts64(tbase + X0_OFF + o, a0, a1);
        sts64(tbase + X1_OFF + o, b0, b1);
        sts64(tbase + X2_OFF + o, c0, c1);
    }
#pragma unroll
    for (int i = 0; i < 2; i++) {
        int uw = tid * 2 + i;
        int row = uw >> 3, c = uw & 7;
        uint32_t o = swz((uint32_t)(row * 128 + c * 16));
        sts128(tbase + W0_OFF + o, r.w0[i]);
        sts128(tbase + W1_OFF + o, r.w1[i]);
        sts128(tbase + W2_OFF + o, r.w2[i]);
    }
}

// top-2 merge with jax tie rule (lowest index wins on equal values)
__device__ __forceinline__ void upd2(float& v1, int& i1, float& v2, int& i2,
                                     float v, int i) {
    if (v > v1)      { v2 = v1; i2 = i1; v1 = v; i1 = i; }
    else if (v > v2) { v2 = v; i2 = i; }
}
__device__ __forceinline__ void merge2(float& v1, int& i1, float& v2, int& i2,
                                       float w1, int j1, float w2, int j2) {
    if (w1 > v1 || (w1 == v1 && j1 < i1)) {
        float nv2; int ni2;
        if (v1 > w2 || (v1 == w2 && i1 < j2)) { nv2 = v1; ni2 = i1; }
        else                                   { nv2 = w2; ni2 = j2; }
        v1 = w1; i1 = j1; v2 = nv2; i2 = ni2;
    } else if (w1 > v2 || (w1 == v2 && j1 < i2)) {
        v2 = w1; i2 = j1;
    }
}

// ---------- main kernel ----------
__global__ void __launch_bounds__(THREADS, 1)
router_main(const float* __restrict__ X, float* __restrict__ out,
            int n_tokens, int out_size) {
    extern __shared__ __align__(1024) char smem[];
    const uint32_t sb = smem_u32(smem);
    const int tid  = threadIdx.x;
    const int lane = tid & 31;
    const int wid  = tid >> 5;
    const int m0   = blockIdx.x * MTILE;
    const int u    = tid & 15;
    const int tb   = tid >> 4;
    const int tw   = wid * 16;     // warp token slab

    // ldmatrix address components
    const int t8  = lane & 7;
    const int mat = lane >> 3;
    const int rsel = (mat & 1) * 8;
    const int bsel = (mat >> 1) * 16;

    float acc[8][4];
#pragma unroll
    for (int n = 0; n < 8; n++)
#pragma unroll
        for (int j = 0; j < 4; j++) acc[n][j] = 0.0f;

    StageRegs cur, nxt;
    load_stage(X, m0, 0, u, tb, tid, cur);
    store_stage(sb, u, tb, tid, cur);
    __syncthreads();

    for (int s = 0; s < NCH; s++) {
        const int buf = s & 1;
        const bool more = (s + 1 < NCH);
        if (more) load_stage(X, m0, s + 1, u, tb, tid, nxt);

        const uint32_t tbase = sb + buf * STAGE_SZ;
        const int arow = tw + t8 + rsel;

#pragma unroll
        for (int kk = 0; kk < 4; kk++) {
            uint32_t aoff = swz((uint32_t)(arow * 128 + kk * 32 + bsel));
            uint32_t a0[4], a1[4], a2[4];
            ldsm4(a0, tbase + X0_OFF + aoff);
            ldsm4(a1, tbase + X1_OFF + aoff);
            ldsm4(a2, tbase + X2_OFF + aoff);

#pragma unroll
            for (int p = 0; p < 4; p++) {
                uint32_t boff = swz((uint32_t)((p * 16 + t8 + rsel) * 128 + kk * 32 + bsel));
                uint32_t b0[4], b1[4], b2[4];
                ldsm4(b0, tbase + W0_OFF + boff);
                ldsm4(b1, tbase + W1_OFF + boff);
                ldsm4(b2, tbase + W2_OFF + boff);

                float* dA = acc[2 * p];
                float* dB = acc[2 * p + 1];
                // x0w0
                mma16816(dA, a0, b0[0], b0[2]);
                mma16816(dB, a0, b0[1], b0[3]);
                // x1w0
                mma16816(dA, a1, b0[0], b0[2]);
                mma16816(dB, a1, b0[1], b0[3]);
                // x0w1
                mma16816(dA, a0, b1[0], b1[2]);
                mma16816(dB, a0, b1[1], b1[3]);
                // x1w1
                mma16816(dA, a1, b1[0], b1[2]);
                mma16816(dB, a1, b1[1], b1[3]);
                // x2w0
                mma16816(dA, a2, b0[0], b0[2]);
                mma16816(dB, a2, b0[1], b0[3]);
                // x0w2
                mma16816(dA, a0, b2[0], b2[2]);
                mma16816(dB, a0, b2[1], b2[3]);
            }
        }
        __syncthreads();          // everyone done reading buf
        if (more) {
            store_stage(sb + (buf ^ 1) * STAGE_SZ, u, tb, tid, nxt);
            cur = nxt;
            __syncthreads();      // buf^1 ready for next iter
        }
    }

    // ---- epilogue: top-2 from mma fragments ----
    const int lane4 = lane & 3;
    float v1 = -INFINITY, v2 = -INFINITY; int i1 = 0, i2 = 0;   // token tw + lane/4
    float q1 = -INFINITY, q2 = -INFINITY; int j1 = 0, j2 = 0;   // token tw + 8 + lane/4
#pragma unroll
    for (int nt = 0; nt < 8; nt++) {
        int n0 = nt * 8 + lane4 * 2;
        upd2(v1, i1, v2, i2, acc[nt][0], n0);
        upd2(v1, i1, v2, i2, acc[nt][1], n0 + 1);
        upd2(q1, j1, q2, j2, acc[nt][2], n0);
        upd2(q1, j1, q2, j2, acc[nt][3], n0 + 1);
    }
#pragma unroll
    for (int d = 1; d <= 2; d <<= 1) {
        float w1 = __shfl_xor_sync(0xffffffffu, v1, d);
        float w2 = __shfl_xor_sync(0xffffffffu, v2, d);
        int   x1 = __shfl_xor_sync(0xffffffffu, i1, d);
        int   x2 = __shfl_xor_sync(0xffffffffu, i2, d);
        merge2(v1, i1, v2, i2, w1, x1, w2, x2);
        float r1 = __shfl_xor_sync(0xffffffffu, q1, d);
        float r2 = __shfl_xor_sync(0xffffffffu, q2, d);
        int   y1 = __shfl_xor_sync(0xffffffffu, j1, d);
        int   y2 = __shfl_xor_sync(0xffffffffu, j2, d);
        merge2(q1, j1, q2, j2, r1, y1, r2, y2);
    }

    if (lane4 == 0) {
        const int sc = n_tokens * 2;
        {
            int g = m0 + tw + (lane >> 2);
            float e2 = __expf(v2 - v1);
            float inv = 1.0f / (1.0f + e2);
            out[g * 2 + 0] = inv;
            out[g * 2 + 1] = e2 * inv;
            if (out_size >= 2 * sc) {
                out[sc + g * 2 + 0] = (float)i1;
                out[sc + g * 2 + 1] = (float)i2;
            }
        }
        {
            int g = m0 + tw + 8 + (lane >> 2);
            float e2 = __expf(q2 - q1);
            float inv = 1.0f / (1.0f + e2);
            out[g * 2 + 0] = inv;
            out[g * 2 + 1] = e2 * inv;
            if (out_size >= 2 * sc) {
                out[sc + g * 2 + 0] = (float)j1;
                out[sc + g * 2 + 1] = (float)j2;
            }
        }
    }
}

extern "C" void kernel_launch(void* const* d_in, const int* in_sizes, int n_in,
                              void* d_out, int out_size) {
    const float* X = (const float*)d_in[0];
    const float* W = (const float*)d_in[1];
    float* out = (float*)d_out;
    const int n_tokens = in_sizes[0] / DIM;          // 16384

    cudaFuncSetAttribute(router_main, cudaFuncAttributeMaxDynamicSharedMemorySize,
                         SMEM_TOTAL);
    prep_w<<<(NEXP * DIM / 4) / 256, 256>>>(W);
    router_main<<<n_tokens / MTILE, THREADS, SMEM_TOTAL>>>(X, out, n_tokens, out_size);
}

// round 6
// speedup vs baseline: 2.2168x; 1.6365x over previous
#include <cuda_runtime.h>
#include <cuda_fp16.h>
#include <cstdint>
#include <math.h>

// TopK router: logits = X[16384,4096] @ W[64,4096]^T, top-2 + softmax.
// fp32-accurate GEMM via 3-term 2-level fp16 split on portable HMMA
// (mma.sync.m16n8k16.f32.f16.f16.f32):
//   x = x0 + x1s*2^-11,  w = w0 + w1s*2^-11   (x1s,w1s stored pre-scaled)
//   acc0 = sum x0*w0 ; acc1 = sum (x1s*w0 + x0*w1s) ; logit = acc0 + acc1*2^-11
// Missing x1*w1 term ~2^-22 relative -> logit error ~1e-5 abs (std 64).

#define DIM     4096
#define NEXP    64
#define MTILE   64
#define KC      64
#define NCH     (DIM / KC)      // 64
#define THREADS 256
#define INV2048 4.8828125e-4f

// smem stage layout (fp16 tiles, 128B row stride, SW128 swizzle)
#define X0_OFF  0
#define X1_OFF  8192
#define W0_OFF  16384
#define W1_OFF  24576
#define STAGE_SZ 32768
#define SMEM_TOTAL (2 * STAGE_SZ)   // 65536
#define LROW 65

__device__ __half g_w0[NEXP * DIM];
__device__ __half g_w1[NEXP * DIM];

// ---------- helpers ----------
__device__ __forceinline__ uint32_t smem_u32(const void* p) {
    uint32_t a;
    asm("{ .reg .u64 t; cvta.to.shared.u64 t, %1; cvt.u32.u64 %0, t; }" : "=r"(a) : "l"(p));
    return a;
}
__device__ __forceinline__ uint32_t swz(uint32_t o) { return o ^ ((o >> 3) & 0x70); }

__device__ __forceinline__ uint32_t pack_f16(float hi, float lo) {
    uint32_t r;
    asm("cvt.rn.f16x2.f32 %0, %1, %2;" : "=r"(r) : "f"(hi), "f"(lo));
    return r;
}
__device__ __forceinline__ float2 unpack_f16(uint32_t u) {
    __half2 h = *reinterpret_cast<__half2*>(&u);
    return __half22float2(h);   // .x = low half (even k)
}
__device__ __forceinline__ void sts64(uint32_t a, uint32_t x, uint32_t y) {
    asm volatile("st.shared.v2.b32 [%0], {%1, %2};" :: "r"(a), "r"(x), "r"(y) : "memory");
}
__device__ __forceinline__ void sts128(uint32_t a, uint4 v) {
    asm volatile("st.shared.v4.b32 [%0], {%1, %2, %3, %4};"
                 :: "r"(a), "r"(v.x), "r"(v.y), "r"(v.z), "r"(v.w) : "memory");
}
__device__ __forceinline__ void ldsm4(uint32_t r[4], uint32_t addr) {
    asm volatile("ldmatrix.sync.aligned.m8n8.x4.shared.b16 {%0,%1,%2,%3}, [%4];"
                 : "=r"(r[0]), "=r"(r[1]), "=r"(r[2]), "=r"(r[3]) : "r"(addr));
}
__device__ __forceinline__ void mma16816(float d[4], const uint32_t a[4],
                                         uint32_t b0, uint32_t b1) {
    asm volatile("mma.sync.aligned.m16n8k16.row.col.f32.f16.f16.f32 "
                 "{%0,%1,%2,%3}, {%4,%5,%6,%7}, {%8,%9}, {%0,%1,%2,%3};"
                 : "+f"(d[0]), "+f"(d[1]), "+f"(d[2]), "+f"(d[3])
                 : "r"(a[0]), "r"(a[1]), "r"(a[2]), "r"(a[3]), "r"(b0), "r"(b1));
}

// ---------- W 2-level fp16 split (residual pre-scaled by 2^11) ----------
__global__ void prep_w(const float* __restrict__ W) {
    int i = (blockIdx.x * blockDim.x + threadIdx.x) * 4;
    float4 v = *(const float4*)(W + i);
    float vv[4] = {v.x, v.y, v.z, v.w};
#pragma unroll
    for (int j = 0; j < 4; j++) {
        float x = vv[j];
        __half h0 = __float2half_rn(x);
        float r = (x - __half2float(h0)) * 2048.0f;
        g_w0[i + j] = h0;
        g_w1[i + j] = __float2half_rn(r);
    }
}

// ---------- staging ----------
struct StageRegs {
    float4 x[4];
    uint4  w0[2], w1[2];
};

__device__ __forceinline__ void load_stage(const float* __restrict__ X, int m0, int s,
                                           int xrow, int xcol, int tid, StageRegs& r) {
    const int k0 = s * KC;
#pragma unroll
    for (int i = 0; i < 4; i++)
        r.x[i] = *(const float4*)(X + (size_t)(m0 + xrow + i * 16) * DIM + k0 + xcol * 4);
#pragma unroll
    for (int i = 0; i < 2; i++) {
        int uw = tid * 2 + i;
        int row = uw >> 3, c = uw & 7;
        size_t gi = (size_t)row * DIM + k0 + c * 8;
        r.w0[i] = *(const uint4*)(g_w0 + gi);
        r.w1[i] = *(const uint4*)(g_w1 + gi);
    }
}

__device__ __forceinline__ void store_stage(uint32_t tbase, int xrow, int xcol, int tid,
                                            const StageRegs& r) {
#pragma unroll
    for (int i = 0; i < 4; i++) {
        float4 v = r.x[i];
        uint32_t h0 = pack_f16(v.y, v.x);
        uint32_t h1 = pack_f16(v.w, v.z);
        float2 u0 = unpack_f16(h0);
        float2 u1 = unpack_f16(h1);
        uint32_t l0 = pack_f16((v.y - u0.y) * 2048.0f, (v.x - u0.x) * 2048.0f);
        uint32_t l1 = pack_f16((v.w - u1.y) * 2048.0f, (v.z - u1.x) * 2048.0f);
        uint32_t o = swz((uint32_t)((xrow + i * 16) * 128 + xcol * 8));
        sts64(tbase + X0_OFF + o, h0, h1);
        sts64(tbase + X1_OFF + o, l0, l1);
    }
#pragma unroll
    for (int i = 0; i < 2; i++) {
        int uw = tid * 2 + i;
        int row = uw >> 3, c = uw & 7;
        uint32_t o = swz((uint32_t)(row * 128 + c * 16));
        sts128(tbase + W0_OFF + o, r.w0[i]);
        sts128(tbase + W1_OFF + o, r.w1[i]);
    }
}

// ---------- main kernel ----------
__global__ void __launch_bounds__(THREADS, 2)
router_main(const float* __restrict__ X, float* __restrict__ out,
            int n_tokens, int out_size) {
    extern __shared__ __align__(1024) char smem[];
    const uint32_t sb = smem_u32(smem);
    const int tid  = threadIdx.x;
    const int lane = tid & 31;
    const int wid  = tid >> 5;
    const int m0   = blockIdx.x * MTILE;

    // X loader: row 0..15 (+16 per iter), col4 0..15
    const int xrow = tid >> 4;
    const int xcol = tid & 15;

    // compute mapping: warp = token slab (16) x expert half (32)
    const int slab = wid & 3;
    const int half = wid >> 2;
    const int t8   = lane & 7;
    const int mat  = lane >> 3;
    const int rsel = (mat & 1) * 8;
    const int bsel = (mat >> 1) * 16;
    const int arow = slab * 16 + t8 + rsel;

    float acc0[4][4], acc1[4][4];
#pragma unroll
    for (int n = 0; n < 4; n++)
#pragma unroll
        for (int j = 0; j < 4; j++) { acc0[n][j] = 0.0f; acc1[n][j] = 0.0f; }

    StageRegs nxt;
    load_stage(X, m0, 0, xrow, xcol, tid, nxt);
    store_stage(sb, xrow, xcol, tid, nxt);
    __syncthreads();

    for (int s = 0; s < NCH; s++) {
        const int buf = s & 1;
        const bool more = (s + 1 < NCH);
        if (more) load_stage(X, m0, s + 1, xrow, xcol, tid, nxt);

        const uint32_t tbase = sb + buf * STAGE_SZ;
#pragma unroll
        for (int kk = 0; kk < 4; kk++) {
            uint32_t aoff = swz((uint32_t)(arow * 128 + kk * 32 + bsel));
            uint32_t a0[4], a1[4];
            ldsm4(a0, tbase + X0_OFF + aoff);
            ldsm4(a1, tbase + X1_OFF + aoff);
#pragma unroll
            for (int p = 0; p < 2; p++) {
                uint32_t boff = swz((uint32_t)((half * 32 + p * 16 + t8 + rsel) * 128
                                               + kk * 32 + bsel));
                uint32_t b0[4], b1[4];
                ldsm4(b0, tbase + W0_OFF + boff);
                ldsm4(b1, tbase + W1_OFF + boff);

                mma16816(acc0[2 * p],     a0, b0[0], b0[2]);
                mma16816(acc0[2 * p + 1], a0, b0[1], b0[3]);
                mma16816(acc1[2 * p],     a1, b0[0], b0[2]);
                mma16816(acc1[2 * p + 1], a1, b0[1], b0[3]);
                mma16816(acc1[2 * p],     a0, b1[0], b1[2]);
                mma16816(acc1[2 * p + 1], a0, b1[1], b1[3]);
            }
        }
        __syncthreads();          // everyone done reading buf
        if (more) {
            store_stage(sb + (buf ^ 1) * STAGE_SZ, xrow, xcol, tid, nxt);
            __syncthreads();      // buf^1 ready
        }
    }

    // ---- epilogue: combine accs -> smem logits -> serial top-2 + softmax ----
    float* Ls = (float*)smem;     // [64][65], safe after the final __syncthreads
#pragma unroll
    for (int t = 0; t < 2; t++) {
        int tok = slab * 16 + (lane >> 2) + t * 8;
#pragma unroll
        for (int nt = 0; nt < 4; nt++) {
            int e0 = half * 32 + nt * 8 + (lane & 3) * 2;
            Ls[tok * LROW + e0 + 0] = acc0[nt][t * 2 + 0] + acc1[nt][t * 2 + 0] * INV2048;
            Ls[tok * LROW + e0 + 1] = acc0[nt][t * 2 + 1] + acc1[nt][t * 2 + 1] * INV2048;
        }
    }
    __syncthreads();

    if (tid < MTILE) {
        const float* row = Ls + tid * LROW;
        float v1 = -INFINITY, v2 = -INFINITY;
        int i1 = 0, i2 = 0;
#pragma unroll 8
        for (int e = 0; e < NEXP; e++) {
            float v = row[e];
            if (v > v1)      { v2 = v1; i2 = i1; v1 = v; i1 = e; }
            else if (v > v2) { v2 = v;  i2 = e; }
        }
        float e2  = __expf(v2 - v1);
        float inv = 1.0f / (1.0f + e2);
        const int g = m0 + tid;
        out[g * 2 + 0] = inv;
        out[g * 2 + 1] = e2 * inv;
        const int sc = n_tokens * 2;
        if (out_size >= 2 * sc) {
            out[sc + g * 2 + 0] = (float)i1;
            out[sc + g * 2 + 1] = (float)i2;
        }
    }
}

extern "C" void kernel_launch(void* const* d_in, const int* in_sizes, int n_in,
                              void* d_out, int out_size) {
    const float* X = (const float*)d_in[0];
    const float* W = (const float*)d_in[1];
    float* out = (float*)d_out;
    const int n_tokens = in_sizes[0] / DIM;          // 16384

    cudaFuncSetAttribute(router_main, cudaFuncAttributeMaxDynamicSharedMemorySize,
                         SMEM_TOTAL);
    prep_w<<<(NEXP * DIM / 4) / 256, 256>>>(W);
    router_main<<<n_tokens / MTILE, THREADS, SMEM_TOTAL>>>(X, out, n_tokens, out_size);
}

// round 7
// speedup vs baseline: 2.2562x; 1.0178x over previous
#include <cuda_runtime.h>
#include <cuda_fp16.h>
#include <cstdint>
#include <math.h>

// TopK router: logits = X[16384,4096] @ W[64,4096]^T, top-2 + softmax.
// 3-term 2-level fp16 split on mma.sync.m16n8k16 (fp32 accum):
//   x = x0 + x1s*2^-11, w = w0 + w1s*2^-11  (residuals pre-scaled)
//   acc0 = x0w0 ; acc1 = x1s*w0 + x0*w1s ; logit = acc0 + acc1*2^-11
// Pipeline: double-buffered smem, regs-prefetch LDG 2 stages ahead,
// ONE __syncthreads per stage.

#define DIM     4096
#define NEXP    64
#define MTILE   64
#define KC      64
#define NCH     (DIM / KC)      // 64
#define THREADS 256
#define INV2048 4.8828125e-4f

#define X0_OFF  0
#define X1_OFF  8192
#define W0_OFF  16384
#define W1_OFF  24576
#define STAGE_SZ 32768
#define SMEM_TOTAL (2 * STAGE_SZ)   // 65536
#define LROW 65

__device__ __half g_w0[NEXP * DIM];
__device__ __half g_w1[NEXP * DIM];

// ---------- helpers ----------
__device__ __forceinline__ uint32_t smem_u32(const void* p) {
    uint32_t a;
    asm("{ .reg .u64 t; cvta.to.shared.u64 t, %1; cvt.u32.u64 %0, t; }" : "=r"(a) : "l"(p));
    return a;
}
__device__ __forceinline__ uint32_t swz(uint32_t o) { return o ^ ((o >> 3) & 0x70); }

__device__ __forceinline__ uint32_t pack_f16(float hi, float lo) {
    uint32_t r;
    asm("cvt.rn.f16x2.f32 %0, %1, %2;" : "=r"(r) : "f"(hi), "f"(lo));
    return r;
}
__device__ __forceinline__ float2 unpack_f16(uint32_t u) {
    __half2 h = *reinterpret_cast<__half2*>(&u);
    return __half22float2(h);
}
__device__ __forceinline__ void sts64(uint32_t a, uint32_t x, uint32_t y) {
    asm volatile("st.shared.v2.b32 [%0], {%1, %2};" :: "r"(a), "r"(x), "r"(y) : "memory");
}
__device__ __forceinline__ void sts128(uint32_t a, uint4 v) {
    asm volatile("st.shared.v4.b32 [%0], {%1, %2, %3, %4};"
                 :: "r"(a), "r"(v.x), "r"(v.y), "r"(v.z), "r"(v.w) : "memory");
}
__device__ __forceinline__ void ldsm4(uint32_t r[4], uint32_t addr) {
    asm volatile("ldmatrix.sync.aligned.m8n8.x4.shared.b16 {%0,%1,%2,%3}, [%4];"
                 : "=r"(r[0]), "=r"(r[1]), "=r"(r[2]), "=r"(r[3]) : "r"(addr));
}
__device__ __forceinline__ void mma16816(float d[4], const uint32_t a[4],
                                         uint32_t b0, uint32_t b1) {
    asm volatile("mma.sync.aligned.m16n8k16.row.col.f32.f16.f16.f32 "
                 "{%0,%1,%2,%3}, {%4,%5,%6,%7}, {%8,%9}, {%0,%1,%2,%3};"
                 : "+f"(d[0]), "+f"(d[1]), "+f"(d[2]), "+f"(d[3])
                 : "r"(a[0]), "r"(a[1]), "r"(a[2]), "r"(a[3]), "r"(b0), "r"(b1));
}

// ---------- W 2-level fp16 split (residual pre-scaled by 2^11) ----------
__global__ void prep_w(const float* __restrict__ W) {
    int i = (blockIdx.x * blockDim.x + threadIdx.x) * 4;
    float4 v = *(const float4*)(W + i);
    float vv[4] = {v.x, v.y, v.z, v.w};
#pragma unroll
    for (int j = 0; j < 4; j++) {
        float x = vv[j];
        __half h0 = __float2half_rn(x);
        float r = (x - __half2float(h0)) * 2048.0f;
        g_w0[i + j] = h0;
        g_w1[i + j] = __float2half_rn(r);
    }
}

// ---------- staging ----------
struct StageRegs {
    float4 x[4];
    uint4  w0[2], w1[2];
};

__device__ __forceinline__ void load_stage(const float* __restrict__ X, int m0, int s,
                                           int xrow, int xcol, int tid, StageRegs& r) {
    const int k0 = s * KC;
#pragma unroll
    for (int i = 0; i < 4; i++)
        r.x[i] = *(const float4*)(X + (size_t)(m0 + xrow + i * 16) * DIM + k0 + xcol * 4);
#pragma unroll
    for (int i = 0; i < 2; i++) {
        int uw = tid * 2 + i;
        int row = uw >> 3, c = uw & 7;
        size_t gi = (size_t)row * DIM + k0 + c * 8;
        r.w0[i] = *(const uint4*)(g_w0 + gi);
        r.w1[i] = *(const uint4*)(g_w1 + gi);
    }
}

__device__ __forceinline__ void store_stage(uint32_t tbase, int xrow, int xcol, int tid,
                                            const StageRegs& r) {
#pragma unroll
    for (int i = 0; i < 4; i++) {
        float4 v = r.x[i];
        uint32_t h0 = pack_f16(v.y, v.x);
        uint32_t h1 = pack_f16(v.w, v.z);
        float2 u0 = unpack_f16(h0);
        float2 u1 = unpack_f16(h1);
        uint32_t l0 = pack_f16((v.y - u0.y) * 2048.0f, (v.x - u0.x) * 2048.0f);
        uint32_t l1 = pack_f16((v.w - u1.y) * 2048.0f, (v.z - u1.x) * 2048.0f);
        uint32_t o = swz((uint32_t)((xrow + i * 16) * 128 + xcol * 8));
        sts64(tbase + X0_OFF + o, h0, h1);
        sts64(tbase + X1_OFF + o, l0, l1);
    }
#pragma unroll
    for (int i = 0; i < 2; i++) {
        int uw = tid * 2 + i;
        int row = uw >> 3, c = uw & 7;
        uint32_t o = swz((uint32_t)(row * 128 + c * 16));
        sts128(tbase + W0_OFF + o, r.w0[i]);
        sts128(tbase + W1_OFF + o, r.w1[i]);
    }
}

// ---------- main kernel ----------
__global__ void __launch_bounds__(THREADS, 2)
router_main(const float* __restrict__ X, float* __restrict__ out,
            int n_tokens, int out_size) {
    extern __shared__ __align__(1024) char smem[];
    const uint32_t sb = smem_u32(smem);
    const int tid  = threadIdx.x;
    const int lane = tid & 31;
    const int wid  = tid >> 5;
    const int m0   = blockIdx.x * MTILE;

    const int xrow = tid >> 4;
    const int xcol = tid & 15;

    const int slab = wid & 3;
    const int half = wid >> 2;
    const int t8   = lane & 7;
    const int mat  = lane >> 3;
    const int rsel = (mat & 1) * 8;
    const int bsel = (mat >> 1) * 16;
    const int arow = slab * 16 + t8 + rsel;

    float acc0[4][4], acc1[4][4];
#pragma unroll
    for (int n = 0; n < 4; n++)
#pragma unroll
        for (int j = 0; j < 4; j++) { acc0[n][j] = 0.0f; acc1[n][j] = 0.0f; }

    // prologue: stage0 -> smem buf0; stage1 -> regs
    StageRegs regs;
    load_stage(X, m0, 0, xrow, xcol, tid, regs);
    store_stage(sb, xrow, xcol, tid, regs);
    load_stage(X, m0, 1, xrow, xcol, tid, regs);
    __syncthreads();

    for (int s = 0; s < NCH; s++) {
        // STS stage s+1 into buf[(s+1)&1] (safe: compute(s-1) retired at last sync)
        if (s + 1 < NCH)
            store_stage(sb + ((s + 1) & 1) * STAGE_SZ, xrow, xcol, tid, regs);
        // LDG stage s+2 -> regs (2-stage distance hides latency)
        if (s + 2 < NCH)
            load_stage(X, m0, s + 2, xrow, xcol, tid, regs);

        const uint32_t tbase = sb + (s & 1) * STAGE_SZ;
#pragma unroll
        for (int kk = 0; kk < 4; kk++) {
            uint32_t aoff = swz((uint32_t)(arow * 128 + kk * 32 + bsel));
            uint32_t a0[4], a1[4];
            ldsm4(a0, tbase + X0_OFF + aoff);
            ldsm4(a1, tbase + X1_OFF + aoff);
#pragma unroll
            for (int p = 0; p < 2; p++) {
                uint32_t boff = swz((uint32_t)((half * 32 + p * 16 + t8 + rsel) * 128
                                               + kk * 32 + bsel));
                uint32_t b0[4], b1[4];
                ldsm4(b0, tbase + W0_OFF + boff);
                ldsm4(b1, tbase + W1_OFF + boff);

                mma16816(acc0[2 * p],     a0, b0[0], b0[2]);
                mma16816(acc0[2 * p + 1], a0, b0[1], b0[3]);
                mma16816(acc1[2 * p],     a1, b0[0], b0[2]);
                mma16816(acc1[2 * p + 1], a1, b0[1], b0[3]);
                mma16816(acc1[2 * p],     a0, b1[0], b1[2]);
                mma16816(acc1[2 * p + 1], a0, b1[1], b1[3]);
            }
        }
        __syncthreads();   // one barrier per stage
    }

    // ---- epilogue ----
    float* Ls = (float*)smem;     // [64][65]
#pragma unroll
    for (int t = 0; t < 2; t++) {
        int tok = slab * 16 + (lane >> 2) + t * 8;
#pragma unroll
        for (int nt = 0; nt < 4; nt++) {
            int e0 = half * 32 + nt * 8 + (lane & 3) * 2;
            Ls[tok * LROW + e0 + 0] = acc0[nt][t * 2 + 0] + acc1[nt][t * 2 + 0] * INV2048;
            Ls[tok * LROW + e0 + 1] = acc0[nt][t * 2 + 1] + acc1[nt][t * 2 + 1] * INV2048;
        }
    }
    __syncthreads();

    if (tid < MTILE) {
        const float* row = Ls + tid * LROW;
        float v1 = -INFINITY, v2 = -INFINITY;
        int i1 = 0, i2 = 0;
#pragma unroll 8
        for (int e = 0; e < NEXP; e++) {
            float v = row[e];
            if (v > v1)      { v2 = v1; i2 = i1; v1 = v; i1 = e; }
            else if (v > v2) { v2 = v;  i2 = e; }
        }
        float e2  = __expf(v2 - v1);
        float inv = 1.0f / (1.0f + e2);
        const int g = m0 + tid;
        out[g * 2 + 0] = inv;
        out[g * 2 + 1] = e2 * inv;
        const int sc = n_tokens * 2;
        if (out_size >= 2 * sc) {
            out[sc + g * 2 + 0] = (float)i1;
            out[sc + g * 2 + 1] = (float)i2;
        }
    }
}

extern "C" void kernel_launch(void* const* d_in, const int* in_sizes, int n_in,
                              void* d_out, int out_size) {
    const float* X = (const float*)d_in[0];
    const float* W = (const float*)d_in[1];
    float* out = (float*)d_out;
    const int n_tokens = in_sizes[0] / DIM;          // 16384

    cudaFuncSetAttribute(router_main, cudaFuncAttributeMaxDynamicSharedMemorySize,
                         SMEM_TOTAL);
    prep_w<<<(NEXP * DIM / 4) / 256, 256>>>(W);
    router_main<<<n_tokens / MTILE, THREADS, SMEM_TOTAL>>>(X, out, n_tokens, out_size);
}

// round 8
// speedup vs baseline: 2.3030x; 1.0207x over previous
#include <cuda_runtime.h>
#include <cuda_fp16.h>
#include <cstdint>
#include <math.h>

// TopK router: logits = X[16384,4096] @ W[64,4096]^T, top-2 + softmax.
// 3-term 2-level fp16 split on mma.sync.m16n8k16 (fp32 accum):
//   x = x0 + x1s*2^-11, w = w0 + w1s*2^-11  (residuals pre-scaled)
//   acc0 = x0w0 ; acc1 = x1s*w0 + x0*w1s ; logit = acc0 + acc1*2^-11
// Pipeline: double-buffered smem; X via LDG->regs->convert->STS (distance 2);
// W via cp.async.cg direct GMEM->smem (distance 1); one barrier per stage;
// 3 CTAs/SM (launch_bounds 256,3) for latency hiding.

#define DIM     4096
#define NEXP    64
#define MTILE   64
#define KC      64
#define NCH     (DIM / KC)      // 64
#define THREADS 256
#define INV2048 4.8828125e-4f

#define X0_OFF  0
#define X1_OFF  8192
#define W0_OFF  16384
#define W1_OFF  24576
#define STAGE_SZ 32768
#define SMEM_TOTAL (2 * STAGE_SZ)   // 65536
#define LROW 65

__device__ __half g_w0[NEXP * DIM];
__device__ __half g_w1[NEXP * DIM];

// ---------- helpers ----------
__device__ __forceinline__ uint32_t smem_u32(const void* p) {
    uint32_t a;
    asm("{ .reg .u64 t; cvta.to.shared.u64 t, %1; cvt.u32.u64 %0, t; }" : "=r"(a) : "l"(p));
    return a;
}
__device__ __forceinline__ uint32_t swz(uint32_t o) { return o ^ ((o >> 3) & 0x70); }

__device__ __forceinline__ uint32_t pack_f16(float hi, float lo) {
    uint32_t r;
    asm("cvt.rn.f16x2.f32 %0, %1, %2;" : "=r"(r) : "f"(hi), "f"(lo));
    return r;
}
__device__ __forceinline__ float2 unpack_f16(uint32_t u) {
    __half2 h = *reinterpret_cast<__half2*>(&u);
    return __half22float2(h);
}
__device__ __forceinline__ void sts64(uint32_t a, uint32_t x, uint32_t y) {
    asm volatile("st.shared.v2.b32 [%0], {%1, %2};" :: "r"(a), "r"(x), "r"(y) : "memory");
}
__device__ __forceinline__ void cpasync16(uint32_t saddr, const void* g) {
    asm volatile("cp.async.cg.shared.global [%0], [%1], 16;"
                 :: "r"(saddr), "l"(g) : "memory");
}
#define CP_COMMIT() asm volatile("cp.async.commit_group;" ::: "memory")
#define CP_WAIT0()  asm volatile("cp.async.wait_group 0;" ::: "memory")

__device__ __forceinline__ void ldsm4(uint32_t r[4], uint32_t addr) {
    asm volatile("ldmatrix.sync.aligned.m8n8.x4.shared.b16 {%0,%1,%2,%3}, [%4];"
                 : "=r"(r[0]), "=r"(r[1]), "=r"(r[2]), "=r"(r[3]) : "r"(addr));
}
__device__ __forceinline__ void mma16816(float d[4], const uint32_t a[4],
                                         uint32_t b0, uint32_t b1) {
    asm volatile("mma.sync.aligned.m16n8k16.row.col.f32.f16.f16.f32 "
                 "{%0,%1,%2,%3}, {%4,%5,%6,%7}, {%8,%9}, {%0,%1,%2,%3};"
                 : "+f"(d[0]), "+f"(d[1]), "+f"(d[2]), "+f"(d[3])
                 : "r"(a[0]), "r"(a[1]), "r"(a[2]), "r"(a[3]), "r"(b0), "r"(b1));
}

// ---------- W 2-level fp16 split (residual pre-scaled by 2^11) ----------
__global__ void prep_w(const float* __restrict__ W) {
    int i = (blockIdx.x * blockDim.x + threadIdx.x) * 4;
    float4 v = *(const float4*)(W + i);
    float vv[4] = {v.x, v.y, v.z, v.w};
#pragma unroll
    for (int j = 0; j < 4; j++) {
        float x = vv[j];
        __half h0 = __float2half_rn(x);
        float r = (x - __half2float(h0)) * 2048.0f;
        g_w0[i + j] = h0;
        g_w1[i + j] = __float2half_rn(r);
    }
}

// ---------- staging ----------
__device__ __forceinline__ void load_x(const float* __restrict__ xg, int s, float4 x[4]) {
#pragma unroll
    for (int i = 0; i < 4; i++)
        x[i] = *(const float4*)(xg + (size_t)i * 16 * DIM + s * KC);
}

__device__ __forceinline__ void store_x(uint32_t tbase, int xrow, int xcol,
                                        const float4 x[4]) {
#pragma unroll
    for (int i = 0; i < 4; i++) {
        float4 v = x[i];
        uint32_t h0 = pack_f16(v.y, v.x);
        uint32_t h1 = pack_f16(v.w, v.z);
        float2 u0 = unpack_f16(h0);
        float2 u1 = unpack_f16(h1);
        uint32_t l0 = pack_f16((v.y - u0.y) * 2048.0f, (v.x - u0.x) * 2048.0f);
        uint32_t l1 = pack_f16((v.w - u1.y) * 2048.0f, (v.z - u1.x) * 2048.0f);
        uint32_t o = swz((uint32_t)((xrow + i * 16) * 128 + xcol * 8));
        sts64(tbase + X0_OFF + o, h0, h1);
        sts64(tbase + X1_OFF + o, l0, l1);
    }
}

__device__ __forceinline__ void stage_w(uint32_t tbase, int s, int tid) {
    const int k0 = s * KC;
#pragma unroll
    for (int i = 0; i < 2; i++) {
        int uw = tid * 2 + i;
        int row = uw >> 3, c = uw & 7;
        size_t gi = (size_t)row * DIM + k0 + c * 8;
        uint32_t o = swz((uint32_t)(row * 128 + c * 16));
        cpasync16(tbase + W0_OFF + o, g_w0 + gi);
        cpasync16(tbase + W1_OFF + o, g_w1 + gi);
    }
}

// ---------- main kernel ----------
__global__ void __launch_bounds__(THREADS, 3)
router_main(const float* __restrict__ X, float* __restrict__ out,
            int n_tokens, int out_size) {
    extern __shared__ __align__(1024) char smem[];
    const uint32_t sb = smem_u32(smem);
    const int tid  = threadIdx.x;
    const int lane = tid & 31;
    const int wid  = tid >> 5;
    const int m0   = blockIdx.x * MTILE;

    const int xrow = tid >> 4;
    const int xcol = tid & 15;
    const float* xg = X + (size_t)(m0 + xrow) * DIM + xcol * 4;

    const int slab = wid & 3;
    const int half = wid >> 2;
    const int t8   = lane & 7;
    const int mat  = lane >> 3;
    const int rsel = (mat & 1) * 8;
    const int bsel = (mat >> 1) * 16;
    const int arow = slab * 16 + t8 + rsel;

    float acc0[4][4], acc1[4][4];
#pragma unroll
    for (int n = 0; n < 4; n++)
#pragma unroll
        for (int j = 0; j < 4; j++) { acc0[n][j] = 0.0f; acc1[n][j] = 0.0f; }

    // prologue: W(0)+X(0) -> buf0; X(1) -> regs (in flight)
    float4 xr[4];
    stage_w(sb, 0, tid);
    CP_COMMIT();
    load_x(xg, 0, xr);
    store_x(sb, xrow, xcol, xr);
    load_x(xg, 1, xr);
    CP_WAIT0();
    __syncthreads();

    for (int s = 0; s < NCH; s++) {
        // stage s+1 into buf[(s+1)&1] (compute(s-1) retired at last barrier)
        if (s + 1 < NCH) {
            const uint32_t nb = sb + ((s + 1) & 1) * STAGE_SZ;
            store_x(nb, xrow, xcol, xr);          // X(s+1) from regs
            stage_w(nb, s + 1, tid);              // W(s+1) async
            CP_COMMIT();
        }
        if (s + 2 < NCH)
            load_x(xg, s + 2, xr);                // X(s+2) -> regs

        const uint32_t tbase = sb + (s & 1) * STAGE_SZ;
#pragma unroll
        for (int kk = 0; kk < 4; kk++) {
            uint32_t aoff = swz((uint32_t)(arow * 128 + kk * 32 + bsel));
            uint32_t a0[4], a1[4];
            ldsm4(a0, tbase + X0_OFF + aoff);
            ldsm4(a1, tbase + X1_OFF + aoff);
#pragma unroll
            for (int p = 0; p < 2; p++) {
                uint32_t boff = swz((uint32_t)((half * 32 + p * 16 + t8 + rsel) * 128
                                               + kk * 32 + bsel));
                uint32_t b0[4], b1[4];
                ldsm4(b0, tbase + W0_OFF + boff);
                ldsm4(b1, tbase + W1_OFF + boff);

                mma16816(acc0[2 * p],     a0, b0[0], b0[2]);
                mma16816(acc0[2 * p + 1], a0, b0[1], b0[3]);
                mma16816(acc1[2 * p],     a1, b0[0], b0[2]);
                mma16816(acc1[2 * p + 1], a1, b0[1], b0[3]);
                mma16816(acc1[2 * p],     a0, b1[0], b1[2]);
                mma16816(acc1[2 * p + 1], a0, b1[1], b1[3]);
            }
        }
        if (s + 1 < NCH) CP_WAIT0();   // W(s+1) landed
        __syncthreads();               // one barrier per stage
    }

    // ---- epilogue ----
    float* Ls = (float*)smem;     // [64][65]
#pragma unroll
    for (int t = 0; t < 2; t++) {
        int tok = slab * 16 + (lane >> 2) + t * 8;
#pragma unroll
        for (int nt = 0; nt < 4; nt++) {
            int e0 = half * 32 + nt * 8 + (lane & 3) * 2;
            Ls[tok * LROW + e0 + 0] = acc0[nt][t * 2 + 0] + acc1[nt][t * 2 + 0] * INV2048;
            Ls[tok * LROW + e0 + 1] = acc0[nt][t * 2 + 1] + acc1[nt][t * 2 + 1] * INV2048;
        }
    }
    __syncthreads();

    if (tid < MTILE) {
        const float* row = Ls + tid * LROW;
        float v1 = -INFINITY, v2 = -INFINITY;
        int i1 = 0, i2 = 0;
#pragma unroll 8
        for (int e = 0; e < NEXP; e++) {
            float v = row[e];
            if (v > v1)      { v2 = v1; i2 = i1; v1 = v; i1 = e; }
            else if (v > v2) { v2 = v;  i2 = e; }
        }
        float e2  = __expf(v2 - v1);
        float inv = 1.0f / (1.0f + e2);
        const int g = m0 + tid;
        out[g * 2 + 0] = inv;
        out[g * 2 + 1] = e2 * inv;
        const int sc = n_tokens * 2;
        if (out_size >= 2 * sc) {
            out[sc + g * 2 + 0] = (float)i1;
            out[sc + g * 2 + 1] = (float)i2;
        }
    }
}

extern "C" void kernel_launch(void* const* d_in, const int* in_sizes, int n_in,
                              void* d_out, int out_size) {
    const float* X = (const float*)d_in[0];
    const float* W = (const float*)d_in[1];
    float* out = (float*)d_out;
    const int n_tokens = in_sizes[0] / DIM;          // 16384

    cudaFuncSetAttribute(router_main, cudaFuncAttributeMaxDynamicSharedMemorySize,
                         SMEM_TOTAL);
    prep_w<<<(NEXP * DIM / 4) / 256, 256>>>(W);
    router_main<<<n_tokens / MTILE, THREADS, SMEM_TOTAL>>>(X, out, n_tokens, out_size);
}

// round 9
// speedup vs baseline: 2.3421x; 1.0170x over previous
#include <cuda_runtime.h>
#include <cuda_fp16.h>
#include <cstdint>
#include <math.h>

// TopK router: logits = X[16384,4096] @ W[64,4096]^T, top-2 + softmax.
// 3-term 2-level fp16 split on mma.sync.m16n8k16 (fp32 accum), split-K=2:
//   grid (256 token-tiles x 2 K-halves) -> partial logits in g_part;
//   reduce kernel sums halves, top-2 + softmax.

#define DIM     4096
#define NEXP    64
#define MTILE   64
#define KC      64
#define KSPLIT  2
#define KHALF   (DIM / KSPLIT)      // 2048
#define NCH_H   (KHALF / KC)        // 32 stages per CTA
#define NTOK    16384
#define THREADS 256
#define INV2048 4.8828125e-4f

#define X0_OFF  0
#define X1_OFF  8192
#define W0_OFF  16384
#define W1_OFF  24576
#define STAGE_SZ 32768
#define SMEM_TOTAL (2 * STAGE_SZ)   // 65536
#define LROW 65

__device__ __half g_w0[NEXP * DIM];
__device__ __half g_w1[NEXP * DIM];
__device__ float  g_part[KSPLIT * NTOK * NEXP];   // 8 MB partial logits

// ---------- helpers ----------
__device__ __forceinline__ uint32_t smem_u32(const void* p) {
    uint32_t a;
    asm("{ .reg .u64 t; cvta.to.shared.u64 t, %1; cvt.u32.u64 %0, t; }" : "=r"(a) : "l"(p));
    return a;
}
__device__ __forceinline__ uint32_t swz(uint32_t o) { return o ^ ((o >> 3) & 0x70); }

__device__ __forceinline__ uint32_t pack_f16(float hi, float lo) {
    uint32_t r;
    asm("cvt.rn.f16x2.f32 %0, %1, %2;" : "=r"(r) : "f"(hi), "f"(lo));
    return r;
}
__device__ __forceinline__ float2 unpack_f16(uint32_t u) {
    __half2 h = *reinterpret_cast<__half2*>(&u);
    return __half22float2(h);
}
__device__ __forceinline__ void sts64(uint32_t a, uint32_t x, uint32_t y) {
    asm volatile("st.shared.v2.b32 [%0], {%1, %2};" :: "r"(a), "r"(x), "r"(y) : "memory");
}
__device__ __forceinline__ void cpasync16(uint32_t saddr, const void* g) {
    asm volatile("cp.async.cg.shared.global [%0], [%1], 16;"
                 :: "r"(saddr), "l"(g) : "memory");
}
#define CP_COMMIT() asm volatile("cp.async.commit_group;" ::: "memory")
#define CP_WAIT0()  asm volatile("cp.async.wait_group 0;" ::: "memory")

__device__ __forceinline__ void ldsm4(uint32_t r[4], uint32_t addr) {
    asm volatile("ldmatrix.sync.aligned.m8n8.x4.shared.b16 {%0,%1,%2,%3}, [%4];"
                 : "=r"(r[0]), "=r"(r[1]), "=r"(r[2]), "=r"(r[3]) : "r"(addr));
}
__device__ __forceinline__ void mma16816(float d[4], const uint32_t a[4],
                                         uint32_t b0, uint32_t b1) {
    asm volatile("mma.sync.aligned.m16n8k16.row.col.f32.f16.f16.f32 "
                 "{%0,%1,%2,%3}, {%4,%5,%6,%7}, {%8,%9}, {%0,%1,%2,%3};"
                 : "+f"(d[0]), "+f"(d[1]), "+f"(d[2]), "+f"(d[3])
                 : "r"(a[0]), "r"(a[1]), "r"(a[2]), "r"(a[3]), "r"(b0), "r"(b1));
}

// ---------- W 2-level fp16 split (residual pre-scaled by 2^11) ----------
__global__ void prep_w(const float* __restrict__ W) {
    int i = (blockIdx.x * blockDim.x + threadIdx.x) * 4;
    float4 v = *(const float4*)(W + i);
    float vv[4] = {v.x, v.y, v.z, v.w};
#pragma unroll
    for (int j = 0; j < 4; j++) {
        float x = vv[j];
        __half h0 = __float2half_rn(x);
        float r = (x - __half2float(h0)) * 2048.0f;
        g_w0[i + j] = h0;
        g_w1[i + j] = __float2half_rn(r);
    }
}

// ---------- staging ----------
__device__ __forceinline__ void load_x(const float* __restrict__ xg, int s, float4 x[4]) {
#pragma unroll
    for (int i = 0; i < 4; i++)
        x[i] = *(const float4*)(xg + (size_t)i * 16 * DIM + s * KC);
}

__device__ __forceinline__ void store_x(uint32_t tbase, int xrow, int xcol,
                                        const float4 x[4]) {
#pragma unroll
    for (int i = 0; i < 4; i++) {
        float4 v = x[i];
        uint32_t h0 = pack_f16(v.y, v.x);
        uint32_t h1 = pack_f16(v.w, v.z);
        float2 u0 = unpack_f16(h0);
        float2 u1 = unpack_f16(h1);
        uint32_t l0 = pack_f16((v.y - u0.y) * 2048.0f, (v.x - u0.x) * 2048.0f);
        uint32_t l1 = pack_f16((v.w - u1.y) * 2048.0f, (v.z - u1.x) * 2048.0f);
        uint32_t o = swz((uint32_t)((xrow + i * 16) * 128 + xcol * 8));
        sts64(tbase + X0_OFF + o, h0, h1);
        sts64(tbase + X1_OFF + o, l0, l1);
    }
}

__device__ __forceinline__ void stage_w(uint32_t tbase, int k0, int tid) {
#pragma unroll
    for (int i = 0; i < 2; i++) {
        int uw = tid * 2 + i;
        int row = uw >> 3, c = uw & 7;
        size_t gi = (size_t)row * DIM + k0 + c * 8;
        uint32_t o = swz((uint32_t)(row * 128 + c * 16));
        cpasync16(tbase + W0_OFF + o, g_w0 + gi);
        cpasync16(tbase + W1_OFF + o, g_w1 + gi);
    }
}

// ---------- main kernel (partial GEMM over one K-half) ----------
__global__ void __launch_bounds__(THREADS, 3)
router_main(const float* __restrict__ X) {
    extern __shared__ __align__(1024) char smem[];
    const uint32_t sb = smem_u32(smem);
    const int tid  = threadIdx.x;
    const int lane = tid & 31;
    const int wid  = tid >> 5;
    const int m0   = blockIdx.x * MTILE;
    const int kh   = blockIdx.y;
    const int kbase = kh * KHALF;

    const int xrow = tid >> 4;
    const int xcol = tid & 15;
    const float* xg = X + (size_t)(m0 + xrow) * DIM + kbase + xcol * 4;

    const int slab = wid & 3;
    const int half = wid >> 2;
    const int t8   = lane & 7;
    const int mat  = lane >> 3;
    const int rsel = (mat & 1) * 8;
    const int bsel = (mat >> 1) * 16;
    const int arow = slab * 16 + t8 + rsel;

    float acc0[4][4], acc1[4][4];
#pragma unroll
    for (int n = 0; n < 4; n++)
#pragma unroll
        for (int j = 0; j < 4; j++) { acc0[n][j] = 0.0f; acc1[n][j] = 0.0f; }

    // prologue: W(0)+X(0) -> buf0; X(1) -> regs (in flight)
    float4 xr[4];
    stage_w(sb, kbase, tid);
    CP_COMMIT();
    load_x(xg, 0, xr);
    store_x(sb, xrow, xcol, xr);
    load_x(xg, 1, xr);
    CP_WAIT0();
    __syncthreads();

    for (int s = 0; s < NCH_H; s++) {
        if (s + 1 < NCH_H) {
            const uint32_t nb = sb + ((s + 1) & 1) * STAGE_SZ;
            store_x(nb, xrow, xcol, xr);
            stage_w(nb, kbase + (s + 1) * KC, tid);
            CP_COMMIT();
        }
        if (s + 2 < NCH_H)
            load_x(xg, s + 2, xr);

        const uint32_t tbase = sb + (s & 1) * STAGE_SZ;
#pragma unroll
        for (int kk = 0; kk < 4; kk++) {
            uint32_t aoff = swz((uint32_t)(arow * 128 + kk * 32 + bsel));
            uint32_t a0[4], a1[4];
            ldsm4(a0, tbase + X0_OFF + aoff);
            ldsm4(a1, tbase + X1_OFF + aoff);
#pragma unroll
            for (int p = 0; p < 2; p++) {
                uint32_t boff = swz((uint32_t)((half * 32 + p * 16 + t8 + rsel) * 128
                                               + kk * 32 + bsel));
                uint32_t b0[4], b1[4];
                ldsm4(b0, tbase + W0_OFF + boff);
                ldsm4(b1, tbase + W1_OFF + boff);

                mma16816(acc0[2 * p],     a0, b0[0], b0[2]);
                mma16816(acc0[2 * p + 1], a0, b0[1], b0[3]);
                mma16816(acc1[2 * p],     a1, b0[0], b0[2]);
                mma16816(acc1[2 * p + 1], a1, b0[1], b0[3]);
                mma16816(acc1[2 * p],     a0, b1[0], b1[2]);
                mma16816(acc1[2 * p + 1], a0, b1[1], b1[3]);
            }
        }
        if (s + 1 < NCH_H) CP_WAIT0();
        __syncthreads();
    }

    // ---- epilogue: combine -> smem -> coalesced partial write ----
    float* Ls = (float*)smem;     // [64][65]
#pragma unroll
    for (int t = 0; t < 2; t++) {
        int tok = slab * 16 + (lane >> 2) + t * 8;
#pragma unroll
        for (int nt = 0; nt < 4; nt++) {
            int e0 = half * 32 + nt * 8 + (lane & 3) * 2;
            Ls[tok * LROW + e0 + 0] = acc0[nt][t * 2 + 0] + acc1[nt][t * 2 + 0] * INV2048;
            Ls[tok * LROW + e0 + 1] = acc0[nt][t * 2 + 1] + acc1[nt][t * 2 + 1] * INV2048;
        }
    }
    __syncthreads();

    float* gp = g_part + ((size_t)kh * NTOK + m0) * NEXP;
#pragma unroll
    for (int k = 0; k < 4; k++) {
        int f = tid + k * THREADS;          // float4 index in [0,1024)
        int token = f >> 4, c4 = f & 15;
        float4 v;
        v.x = Ls[token * LROW + c4 * 4 + 0];
        v.y = Ls[token * LROW + c4 * 4 + 1];
        v.z = Ls[token * LROW + c4 * 4 + 2];
        v.w = Ls[token * LROW + c4 * 4 + 3];
        *(float4*)(gp + token * NEXP + c4 * 4) = v;
    }
}

// ---------- reduce: sum halves, top-2 + softmax ----------
__global__ void __launch_bounds__(THREADS)
reduce_topk(float* __restrict__ out, int out_size) {
    __shared__ float Ls[MTILE * LROW];
    const int tid = threadIdx.x;
    const int m0  = blockIdx.x * MTILE;

    const float4* p0 = (const float4*)(g_part + (size_t)m0 * NEXP);
    const float4* p1 = (const float4*)(g_part + (size_t)NTOK * NEXP + (size_t)m0 * NEXP);
#pragma unroll
    for (int k = 0; k < 4; k++) {
        int f = tid + k * THREADS;
        int token = f >> 4, c4 = f & 15;
        float4 a = p0[f];
        float4 b = p1[f];
        Ls[token * LROW + c4 * 4 + 0] = a.x + b.x;
        Ls[token * LROW + c4 * 4 + 1] = a.y + b.y;
        Ls[token * LROW + c4 * 4 + 2] = a.z + b.z;
        Ls[token * LROW + c4 * 4 + 3] = a.w + b.w;
    }
    __syncthreads();

    if (tid < MTILE) {
        const float* row = Ls + tid * LROW;
        float v1 = -INFINITY, v2 = -INFINITY;
        int i1 = 0, i2 = 0;
#pragma unroll 8
        for (int e = 0; e < NEXP; e++) {
            float v = row[e];
            if (v > v1)      { v2 = v1; i2 = i1; v1 = v; i1 = e; }
            else if (v > v2) { v2 = v;  i2 = e; }
        }
        float e2  = __expf(v2 - v1);
        float inv = 1.0f / (1.0f + e2);
        const int g = m0 + tid;
        out[g * 2 + 0] = inv;
        out[g * 2 + 1] = e2 * inv;
        const int sc = NTOK * 2;
        if (out_size >= 2 * sc) {
            out[sc + g * 2 + 0] = (float)i1;
            out[sc + g * 2 + 1] = (float)i2;
        }
    }
}

extern "C" void kernel_launch(void* const* d_in, const int* in_sizes, int n_in,
                              void* d_out, int out_size) {
    const float* X = (const float*)d_in[0];
    const float* W = (const float*)d_in[1];
    float* out = (float*)d_out;

    cudaFuncSetAttribute(router_main, cudaFuncAttributeMaxDynamicSharedMemorySize,
                         SMEM_TOTAL);
    prep_w<<<(NEXP * DIM / 4) / 256, 256>>>(W);
    router_main<<<dim3(NTOK / MTILE, KSPLIT), THREADS, SMEM_TOTAL>>>(X);
    reduce_topk<<<NTOK / MTILE, THREADS>>>(out, out_size);
}